// round 12
// baseline (speedup 1.0000x reference)
#include <cuda_runtime.h>
#include <cstdint>

// Problem constants
#define NUM_VERTS 6890
#define NUM_FACES 13776
#define IMG_H 1024
#define IMG_W 1024
#define NBATCH 16
#define HW (IMG_H * IMG_W)
#define PLANE_FLOATS (HW * 3)            // 3,145,728 floats per batch plane
#define THREADS 256
#define PIX_PER_THREAD 8
#define PIX_PER_BLOCK (THREADS * PIX_PER_THREAD)    // 2048
#define SEG_FLOATS (PIX_PER_BLOCK * 3)              // 6144 floats = 24KB
#define SEG_F4 (SEG_FLOATS / 4)                     // 1536 float4
#define F4_PER_THREAD (SEG_F4 / THREADS)            // 6

// Precomputed per-face vertex attributes, 64B-aligned rows:
// row f = { v0.xyz _, v1.xyz _, v2.xyz _, pad }. 882KB -> L2-resident.
__device__ __align__(64) float4 g_face_attr[NUM_FACES][4];

// Kernel A: build the face-attr table (batch-0 vertices only; the reference's
// pixel gather never applies a per-batch face offset and batch-0 vertex
// offset is 0, so only batch 0 matters).
__global__ void __launch_bounds__(256) build_face_attr(
    const float* __restrict__ verts,   // (N, V, 3) f32
    const int*   __restrict__ faces)   // (F, 3) i32
{
    const int f = blockIdx.x * blockDim.x + threadIdx.x;
    if (f >= NUM_FACES) return;
    const int i0 = faces[f * 3 + 0];
    const int i1 = faces[f * 3 + 1];
    const int i2 = faces[f * 3 + 2];
    const float* v0 = verts + (size_t)i0 * 3;
    const float* v1 = verts + (size_t)i1 * 3;
    const float* v2 = verts + (size_t)i2 * 3;
    g_face_attr[f][0] = make_float4(v0[0], v0[1], v0[2], 0.0f);
    g_face_attr[f][1] = make_float4(v1[0], v1[1], v1[2], 0.0f);
    g_face_attr[f][2] = make_float4(v2[0], v2[1], v2[2], 0.0f);
}

// Kernel B: 8 pixels/thread (2048 px / block, 512 blocks -> whole grid
// resident in ONE wave). Stage the block's 24KB segment in smem, then
// broadcast to all 16 batch planes with coalesced float4 streaming stores
// distributed across all 256 threads.
__global__ void __launch_bounds__(THREADS) render_kernel(
    const int*   __restrict__ pix,     // (H*W) i32
    const float* __restrict__ bary,    // (H*W, 3) f32
    float* __restrict__ out)           // (16, H, W, 3) f32
{
    __shared__ __align__(16) float seg[SEG_FLOATS];

    const int tid = threadIdx.x;
    const int p0  = blockIdx.x * PIX_PER_BLOCK + tid * PIX_PER_THREAD;

    // ---- All inputs up front: 2x int4 + 6x float4, 8 independent loads ----
    const int4* px4 = reinterpret_cast<const int4*>(pix + p0);
    const int4 pxa = px4[0];
    const int4 pxb = px4[1];
    const int pf[8] = { pxa.x, pxa.y, pxa.z, pxa.w, pxb.x, pxb.y, pxb.z, pxb.w };

    const float4* b4 = reinterpret_cast<const float4*>(bary + (size_t)p0 * 3);
    float bwf[24];
    #pragma unroll
    for (int j = 0; j < 6; j++) {
        const float4 b = b4[j];
        bwf[j * 4 + 0] = b.x; bwf[j * 4 + 1] = b.y;
        bwf[j * 4 + 2] = b.z; bwf[j * 4 + 3] = b.w;
    }

    // ---- Compute 8 pixels; stage in smem (float4 stores) ----
    float4* sp4 = reinterpret_cast<float4*>(seg + tid * (PIX_PER_THREAD * 3));
    #pragma unroll
    for (int h = 0; h < 2; h++) {                 // 2 groups of 4 pixels
        float vals[12];
        #pragma unroll
        for (int i = 0; i < 4; i++) {
            const int pidx = h * 4 + i;
            const int f    = pf[pidx];
            float r0 = 0.0f, r1 = 0.0f, r2 = 0.0f;
            if (f >= 0) {
                // 3 x LDG.128 from one 64B row; table is L2-resident.
                const float4 v0 = __ldg(&g_face_attr[f][0]);
                const float4 v1 = __ldg(&g_face_attr[f][1]);
                const float4 v2 = __ldg(&g_face_attr[f][2]);
                const float w0 = bwf[pidx * 3 + 0];
                const float w1 = bwf[pidx * 3 + 1];
                const float w2 = bwf[pidx * 3 + 2];
                r0 = fmaf(w2, v2.x, fmaf(w1, v1.x, w0 * v0.x));
                r1 = fmaf(w2, v2.y, fmaf(w1, v1.y, w0 * v0.y));
                r2 = fmaf(w2, v2.z, fmaf(w1, v1.z, w0 * v0.z));
            }
            vals[i * 3 + 0] = r0;
            vals[i * 3 + 1] = r1;
            vals[i * 3 + 2] = r2;
        }
        sp4[h * 3 + 0] = make_float4(vals[0], vals[1], vals[2],  vals[3]);
        sp4[h * 3 + 1] = make_float4(vals[4], vals[5], vals[6],  vals[7]);
        sp4[h * 3 + 2] = make_float4(vals[8], vals[9], vals[10], vals[11]);
    }
    __syncthreads();

    // ---- Broadcast segment to all 16 batch planes, fully coalesced ----
    const float4* s4 = reinterpret_cast<const float4*>(seg);   // 1536 float4
    float4 c[F4_PER_THREAD];
    #pragma unroll
    for (int j = 0; j < F4_PER_THREAD; j++)
        c[j] = s4[tid + j * THREADS];

    const size_t seg_base4 = (size_t)blockIdx.x * SEG_F4;
    float4* o4 = reinterpret_cast<float4*>(out);
    #pragma unroll
    for (int b = 0; b < NBATCH; b++) {
        float4* dst = o4 + (size_t)b * (PLANE_FLOATS / 4) + seg_base4;
        #pragma unroll
        for (int j = 0; j < F4_PER_THREAD; j++)
            __stcs(&dst[tid + j * THREADS], c[j]);
    }
}

extern "C" void kernel_launch(void* const* d_in, const int* in_sizes, int n_in,
                              void* d_out, int out_size)
{
    // metadata order: verts_attr (f32), face_tensor (i32), pix_to_face (i32), bary_coords (f32)
    const float* verts = (const float*)d_in[0];
    const int*   faces = (const int*)d_in[1];
    const int*   pix   = (const int*)d_in[2];
    const float* bary  = (const float*)d_in[3];
    float* out = (float*)d_out;

    build_face_attr<<<(NUM_FACES + 255) / 256, 256>>>(verts, faces);
    render_kernel<<<HW / PIX_PER_BLOCK, THREADS>>>(pix, bary, out);  // 512 blocks
}

// round 15
// speedup vs baseline: 1.2438x; 1.2438x over previous
#include <cuda_runtime.h>
#include <cstdint>

// Problem constants
#define NUM_VERTS 6890
#define NUM_FACES 13776
#define IMG_H 1024
#define IMG_W 1024
#define NBATCH 16
#define HW (IMG_H * IMG_W)
#define PLANE_FLOATS (HW * 3)            // 3,145,728 floats per batch plane
#define THREADS 128
#define PIX_PER_THREAD 4
#define PIX_PER_BLOCK (THREADS * PIX_PER_THREAD)    // 512
#define SEG_FLOATS (PIX_PER_BLOCK * 3)              // 1536 floats = 6KB
#define SEG_F4 (SEG_FLOATS / 4)                     // 384 float4
#define F4_PER_THREAD (SEG_F4 / THREADS)            // 3

// Precomputed per-face vertex attributes, 64B-aligned rows:
// row f = { v0.xyz _, v1.xyz _, v2.xyz _, pad }. 882KB -> L2-resident.
__device__ __align__(64) float4 g_face_attr[NUM_FACES][4];

// Kernel A: build the face-attr table (batch-0 vertices only; the reference's
// pixel gather never applies a per-batch face offset and batch-0 vertex
// offset is 0, so only batch 0 matters).
__global__ void __launch_bounds__(256) build_face_attr(
    const float* __restrict__ verts,   // (N, V, 3) f32
    const int*   __restrict__ faces)   // (F, 3) i32
{
    const int f = blockIdx.x * blockDim.x + threadIdx.x;
    if (f >= NUM_FACES) return;
    const int i0 = faces[f * 3 + 0];
    const int i1 = faces[f * 3 + 1];
    const int i2 = faces[f * 3 + 2];
    const float* v0 = verts + (size_t)i0 * 3;
    const float* v1 = verts + (size_t)i1 * 3;
    const float* v2 = verts + (size_t)i2 * 3;
    g_face_attr[f][0] = make_float4(v0[0], v0[1], v0[2], 0.0f);
    g_face_attr[f][1] = make_float4(v1[0], v1[1], v1[2], 0.0f);
    g_face_attr[f][2] = make_float4(v2[0], v2[1], v2[2], 0.0f);
}

// Kernel B: 4 pixels/thread, 128-thread CTAs (2048 blocks). Small CTAs let
// ~12 CTAs reside per SM (48 warps) -> deep warp supply to hide gather
// latency and keep the store stream saturated. Stage 6KB in smem, then
// broadcast to all 16 batch planes with coalesced float4 streaming stores.
__global__ void __launch_bounds__(THREADS) render_kernel(
    const int*   __restrict__ pix,     // (H*W) i32
    const float* __restrict__ bary,    // (H*W, 3) f32
    float* __restrict__ out)           // (16, H, W, 3) f32
{
    __shared__ __align__(16) float seg[SEG_FLOATS];

    const int tid = threadIdx.x;
    const int p0  = blockIdx.x * PIX_PER_BLOCK + tid * PIX_PER_THREAD;

    // ---- pix first (heads the dependent gather chain), then bary ----
    const int4 px = *reinterpret_cast<const int4*>(pix + p0);
    const float4* b4 = reinterpret_cast<const float4*>(bary + (size_t)p0 * 3);
    const float4 bA = b4[0];
    const float4 bB = b4[1];
    const float4 bC = b4[2];

    const int pf[4] = { px.x, px.y, px.z, px.w };
    const float bw[4][3] = {
        { bA.x, bA.y, bA.z },
        { bA.w, bB.x, bB.y },
        { bB.z, bB.w, bC.x },
        { bC.y, bC.z, bC.w }
    };

    // ---- Compute 4 pixels; write into smem segment ----
    float* sp = seg + tid * 12;
    #pragma unroll
    for (int i = 0; i < 4; i++) {
        float r0 = 0.0f, r1 = 0.0f, r2 = 0.0f;
        const int f = pf[i];
        if (f >= 0) {
            // 3 x LDG.128 from a 64B-aligned row; table is L2-resident.
            const float4 v0 = __ldg(&g_face_attr[f][0]);
            const float4 v1 = __ldg(&g_face_attr[f][1]);
            const float4 v2 = __ldg(&g_face_attr[f][2]);
            const float w0 = bw[i][0], w1 = bw[i][1], w2 = bw[i][2];
            r0 = fmaf(w2, v2.x, fmaf(w1, v1.x, w0 * v0.x));
            r1 = fmaf(w2, v2.y, fmaf(w1, v1.y, w0 * v0.y));
            r2 = fmaf(w2, v2.z, fmaf(w1, v1.z, w0 * v0.z));
        }
        sp[i * 3 + 0] = r0;
        sp[i * 3 + 1] = r1;
        sp[i * 3 + 2] = r2;
    }
    __syncthreads();

    // ---- Broadcast segment to all 16 batch planes, fully coalesced ----
    const float4* s4 = reinterpret_cast<const float4*>(seg);   // 384 float4
    const float4 c0 = s4[tid];
    const float4 c1 = s4[tid + THREADS];
    const float4 c2 = s4[tid + 2 * THREADS];

    const size_t seg_base4 = (size_t)blockIdx.x * SEG_F4;
    float4* o4 = reinterpret_cast<float4*>(out);
    #pragma unroll
    for (int b = 0; b < NBATCH; b++) {
        float4* dst = o4 + (size_t)b * (PLANE_FLOATS / 4) + seg_base4;
        __stcs(&dst[tid],               c0);
        __stcs(&dst[tid + THREADS],     c1);
        __stcs(&dst[tid + 2 * THREADS], c2);
    }
}

extern "C" void kernel_launch(void* const* d_in, const int* in_sizes, int n_in,
                              void* d_out, int out_size)
{
    // metadata order: verts_attr (f32), face_tensor (i32), pix_to_face (i32), bary_coords (f32)
    const float* verts = (const float*)d_in[0];
    const int*   faces = (const int*)d_in[1];
    const int*   pix   = (const int*)d_in[2];
    const float* bary  = (const float*)d_in[3];
    float* out = (float*)d_out;

    build_face_attr<<<(NUM_FACES + 255) / 256, 256>>>(verts, faces);
    render_kernel<<<HW / PIX_PER_BLOCK, THREADS>>>(pix, bary, out);  // 2048 blocks
}